// round 3
// baseline (speedup 1.0000x reference)
#include <cuda_runtime.h>
#include <cstdint>

// MonarchOutProjection: out[t, 32p+q] = sum_m R[q][p][m] * h2[t][m][q]
//                       h2[t][m][q]   = sum_k L[m][q][k] * x[t][32k+m]
//
// Design:
//  - gridDim.y = 2: q-half split (q in [0,16) / [16,32)) so L-half + R-half fit smem.
//  - Persistent CTAs: grid (74,2) = 148 CTAs = 1 wave, L/R loaded once per CTA.
//  - 8 tokens/tile, packed as 4 f32x2 pairs -> fma.rn.f32x2 (2x fp32 throughput).
//  - Warp w handles local q = {2w, 2w+1}. Stage1: lane = m. Stage2: lane = (qsel,p2).
//  - All smem arrays pad-strided for zero bank conflicts (513 / 1072 / 129 / 17 / 33).
//  - Register prefetch of next x tile issued between stage1 and stage2.

#define HALF_Q   16
#define TPT      8      // tokens per tile
#define NPAIR    4      // f32x2 pairs per tile
#define THREADS  256
#define GRIDX    74

// shared memory layout (float offsets)
#define OFF_LS   0                 // Ls[32][513]            = 16416 floats
#define OFF_RS   16416             // Rs[16][1072]           = 17152 floats
#define OFF_XS   33568             // xs2: float2[4*1024]    =  8192 floats
#define OFF_H2   41760             // h2s: float2[8*2*129]   =  4128 floats
#define OFF_OUT  45888             // outs[8][32][17]        =  4352 floats
#define SMEM_FLOATS 50240
#define SMEM_BYTES  (SMEM_FLOATS * 4)   // 200960 B  (< 227 KB)

__device__ __forceinline__ unsigned long long pack2(float v) {
    unsigned long long r;
    asm("mov.b64 %0, {%1, %1};" : "=l"(r) : "f"(v));
    return r;
}
__device__ __forceinline__ unsigned long long ffma2(unsigned long long a,
                                                    unsigned long long b,
                                                    unsigned long long c) {
    unsigned long long d;
    asm("fma.rn.f32x2 %0, %1, %2, %3;" : "=l"(d) : "l"(a), "l"(b), "l"(c));
    return d;
}
__device__ __forceinline__ void unpack2(unsigned long long v, float& lo, float& hi) {
    asm("mov.b64 {%0, %1}, %2;" : "=f"(lo), "=f"(hi) : "l"(v));
}

__global__ __launch_bounds__(THREADS, 1)
void monarch_kernel(const float* __restrict__ x,
                    const float* __restrict__ Lg,
                    const float* __restrict__ Rg,
                    float* __restrict__ out,
                    int ntiles)
{
    extern __shared__ float sm[];
    float*  Ls   = sm + OFF_LS;
    float*  Rs   = sm + OFF_RS;
    float2* xs2  = (float2*)(sm + OFF_XS);
    float2* h2s  = (float2*)(sm + OFF_H2);
    float*  outs = sm + OFF_OUT;

    const int tid  = threadIdx.x;
    const int w    = tid >> 5;
    const int lane = tid & 31;
    const int qb   = blockIdx.y * HALF_Q;     // global q base of this half

    // ---- one-time: load L-half and R-half into padded smem ----
    // L[m][q][k] -> Ls[m*513 + ql*32 + k]        (bank = (m + k) & 31, conflict-free)
    for (int idx = tid; idx < 32 * HALF_Q * 32; idx += THREADS) {
        int m = idx >> 9;
        int r = idx & 511;                    // ql*32 + k
        Ls[m * 513 + r] = Lg[m * 1024 + qb * 32 + r];
    }
    // R[q][p][m] -> Rs[ql*1072 + p*33 + m]
    for (int idx = tid; idx < HALF_Q * 32 * 32; idx += THREADS) {
        int ql = idx >> 10;
        int r  = idx & 1023;                  // p*32 + m
        Rs[ql * 1072 + (r >> 5) * 33 + (r & 31)] = Rg[(qb + ql) * 1024 + r];
    }

    // prefetch roles: 64 threads per token pair
    const int pfp = tid >> 6;                 // pair 0..3
    const int pfs = tid & 63;                 // element phase
    float pfA[16], pfB[16];

    int tile = blockIdx.x;
    const int stride = GRIDX;

    if (tile < ntiles) {
        const float* xa = x + (size_t)(tile * TPT + 2 * pfp) * 1024 + pfs;
        #pragma unroll
        for (int j = 0; j < 16; j++) { pfA[j] = xa[64 * j]; pfB[j] = xa[1024 + 64 * j]; }
        float2* xw = xs2 + pfp * 1024 + pfs;
        #pragma unroll
        for (int j = 0; j < 16; j++) xw[64 * j] = make_float2(pfA[j], pfB[j]);
    }
    __syncthreads();

    for (; tile < ntiles; tile += stride) {
        // ================= stage 1: h2[m][q] (lane = m, q = qb + 2w + {0,1}) ========
        {
            unsigned long long acc[2][NPAIR];
            #pragma unroll
            for (int a = 0; a < 2; a++)
                #pragma unroll
                for (int p = 0; p < NPAIR; p++) acc[a][p] = 0ull;

            const float*  lp = Ls + lane * 513 + (2 * w) * 32;   // [k], q+1 at +32
            const float2* vp = xs2 + lane;                       // + p*1024 + k*32

            #pragma unroll
            for (int k = 0; k < 32; k++) {
                unsigned long long L0 = pack2(lp[k]);
                unsigned long long L1 = pack2(lp[32 + k]);
                #pragma unroll
                for (int p = 0; p < NPAIR; p++) {
                    unsigned long long v =
                        *(const unsigned long long*)&vp[p * 1024 + k * 32];
                    acc[0][p] = ffma2(L0, v, acc[0][p]);
                    acc[1][p] = ffma2(L1, v, acc[1][p]);
                }
            }
            // warp-private h2 staging: h2s[w][qsel][p*32 + m] (qsel stride 129 -> pad)
            float2* hw = h2s + w * 258;
            #pragma unroll
            for (int qs = 0; qs < 2; qs++)
                #pragma unroll
                for (int p = 0; p < NPAIR; p++)
                    *(unsigned long long*)&hw[qs * 129 + p * 32 + lane] = acc[qs][p];
        }
        __syncthreads();   // all warps finished reading xs2 (and wrote h2s)

        // ---- register prefetch of next tile (hidden under stage 2) ----
        const int nxt = tile + stride;
        const bool hasNext = nxt < ntiles;
        if (hasNext) {
            const float* xa = x + (size_t)(nxt * TPT + 2 * pfp) * 1024 + pfs;
            #pragma unroll
            for (int j = 0; j < 16; j++) { pfA[j] = xa[64 * j]; pfB[j] = xa[1024 + 64 * j]; }
        }

        // ================= stage 2: out[p][q] (lane = qsel*16 + p2) ================
        {
            const int qsel = lane >> 4;
            const int p2   = lane & 15;
            unsigned long long acc[2][NPAIR];   // [j: p2 / p2+16][pair]
            #pragma unroll
            for (int a = 0; a < 2; a++)
                #pragma unroll
                for (int p = 0; p < NPAIR; p++) acc[a][p] = 0ull;

            const float2* hq = h2s + w * 258 + qsel * 129;           // + p*32 + m
            const float*  rp = Rs + (2 * w + qsel) * 1072 + p2 * 33; // + m, j at +528

            #pragma unroll
            for (int m = 0; m < 32; m++) {
                unsigned long long R0 = pack2(rp[m]);
                unsigned long long R1 = pack2(rp[528 + m]);
                #pragma unroll
                for (int p = 0; p < NPAIR; p++) {
                    unsigned long long h =
                        *(const unsigned long long*)&hq[p * 32 + m];
                    acc[0][p] = ffma2(R0, h, acc[0][p]);
                    acc[1][p] = ffma2(R1, h, acc[1][p]);
                }
            }
            // scatter into padded out staging: outs[t][p][qi], row stride 17
            const int qi = 2 * w + qsel;
            #pragma unroll
            for (int j = 0; j < 2; j++)
                #pragma unroll
                for (int p = 0; p < NPAIR; p++) {
                    float f0, f1;
                    unpack2(acc[j][p], f0, f1);
                    int pp = p2 + 16 * j;
                    outs[(2 * p)     * 544 + pp * 17 + qi] = f0;
                    outs[(2 * p + 1) * 544 + pp * 17 + qi] = f1;
                }
        }

        // commit prefetched tile into xs2 (stage-1 readers already synced past it)
        if (hasNext) {
            float2* xw = xs2 + pfp * 1024 + pfs;
            #pragma unroll
            for (int j = 0; j < 16; j++) xw[64 * j] = make_float2(pfA[j], pfB[j]);
        }
        __syncthreads();   // outs complete + xs2 ready

        // ================= coalesced writeout (64B chunks) =========================
        {
            const size_t gbase = (size_t)tile * TPT * 1024;
            #pragma unroll 4
            for (int idx = tid; idx < TPT * 512; idx += THREADS) {
                int t  = idx >> 9;
                int r  = idx & 511;
                int p  = r >> 4;
                int qi = r & 15;
                out[gbase + (size_t)t * 1024 + p * 32 + qb + qi] =
                    outs[t * 544 + p * 17 + qi];
            }
        }
        __syncthreads();   // outs reusable next iteration
    }
}

extern "C" void kernel_launch(void* const* d_in, const int* in_sizes, int n_in,
                              void* d_out, int out_size)
{
    const float* x  = (const float*)d_in[0];
    const float* Lg = (const float*)d_in[1];
    const float* Rg = (const float*)d_in[2];
    float* out      = (float*)d_out;

    const int tokens = in_sizes[0] / 1024;   // 32768
    const int ntiles = tokens / TPT;         // 4096

    cudaFuncSetAttribute(monarch_kernel,
                         cudaFuncAttributeMaxDynamicSharedMemorySize, SMEM_BYTES);

    dim3 grid(GRIDX, 2);
    monarch_kernel<<<grid, THREADS, SMEM_BYTES>>>(x, Lg, Rg, out, ntiles);
}

// round 4
// speedup vs baseline: 1.0171x; 1.0171x over previous
#include <cuda_runtime.h>
#include <cstdint>

// MonarchOutProjection:
//   h2[t][m][q] = sum_k L[m][q][k] * x[t][32k+m]
//   out[t][32p+q] = sum_m R[q][p][m] * h2[t][m][q]
//
// R4 design:
//  - gridDim (74,2): q-half split (16 q per CTA), 148 CTAs = 1 wave, persistent.
//  - 512 threads (16 warps) -> occ 25% (was 12.5%).
//  - Tile = 16 tokens (8 f32x2 pairs). Warp w: qq = w&3 (4 q), pq = w>>2 (2 pairs).
//    q-reuse = 4, pair-reuse = 2  => ~2 B LDS per FMA (was ~2.5).
//  - x streamed in k-chunks of 8 via 2x8KB double buffer (LDG prefetch -> regs
//    -> STS commit), so full L+R halves + buffers fit 227KB smem.
//  - L stored [q][k][m], R stored [q][m][p]: lane-contiguous LDS, no padding.
//  - h2 staging is warp-private: stage1 warp (qq,pq) feeds stage2 warp (qq,pq),
//    only __syncwarp between stages. h-reads in stage2 are 16B broadcasts.

#define THREADS 512
#define GRIDX   74
#define TPT     16          // tokens per tile
#define KCH     8           // k-values per chunk
#define NCHUNK  4

// shared memory layout (float offsets)
#define OFF_LS   0          // Ls[q][k][m]           16*1024 = 16384
#define OFF_RS   16384      // Rs[q][m][p]           16*1024 = 16384
#define OFF_XS   32768      // xs: f2[2][8][8][32]   = 8192 floats
#define OFF_H2   40960      // h2: f2[16w][8][32]    = 8192 floats
#define OFF_OUT  49152      // outs[16t][16q*33+p]   = 8448 floats
#define SMEM_FLOATS 57600
#define SMEM_BYTES  (SMEM_FLOATS * 4)   // 230400 B

__device__ __forceinline__ unsigned long long pack2(float v) {
    unsigned long long r;
    asm("mov.b64 %0, {%1, %1};" : "=l"(r) : "f"(v));
    return r;
}
__device__ __forceinline__ unsigned long long ffma2(unsigned long long a,
                                                    unsigned long long b,
                                                    unsigned long long c) {
    unsigned long long d;
    asm("fma.rn.f32x2 %0, %1, %2, %3;" : "=l"(d) : "l"(a), "l"(b), "l"(c));
    return d;
}
__device__ __forceinline__ void unpack2(unsigned long long v, float& lo, float& hi) {
    asm("mov.b64 {%0, %1}, %2;" : "=f"(lo), "=f"(hi) : "l"(v));
}

__global__ __launch_bounds__(THREADS, 1)
void monarch_kernel(const float* __restrict__ x,
                    const float* __restrict__ Lg,
                    const float* __restrict__ Rg,
                    float* __restrict__ out,
                    int ntiles)
{
    extern __shared__ float sm[];
    float*  Ls   = sm + OFF_LS;
    float*  Rs   = sm + OFF_RS;
    float2* xs   = (float2*)(sm + OFF_XS);   // [buf*2048 + pair*256 + kk*32 + m]
    float2* h2   = (float2*)(sm + OFF_H2);   // [w*256 + (qs*2+pr)*32 + m]
    float*  outs = sm + OFF_OUT;             // [t*528 + q*33 + p]

    const int tid  = threadIdx.x;
    const int w    = tid >> 5;
    const int lane = tid & 31;
    const int qq   = w & 3;       // q quad: q_local = 4*qq + qs
    const int pq   = w >> 2;      // pair group: pairs {2pq, 2pq+1}
    const int qb   = blockIdx.y * 16;

    // ---- one-time L/R loads (global-coalesced reads, transposed STS) ----
    // Ls[q*1024 + k*32 + m] = Lg[m*1024 + (qb+q)*32 + k]
    for (int j = tid; j < 16384; j += THREADS) {
        int m = j >> 9;              // 0..31
        int r = j & 511;             // q*32 + k
        int q = r >> 5, k = r & 31;
        Ls[q * 1024 + k * 32 + m] = Lg[m * 1024 + qb * 32 + r];
    }
    // Rs[q*1024 + m*32 + p] = Rg[(qb+q)*1024 + p*32 + m]
    for (int j = tid; j < 16384; j += THREADS) {
        int q = j >> 10;
        int r = j & 1023;            // p*32 + m
        int p = r >> 5, m = r & 31;
        Rs[q * 1024 + m * 32 + p] = Rg[(qb + q) * 1024 + r];
    }

    int tile = blockIdx.x;

    // ---- preload chunk 0 of first tile into buf 0 ----
    if (tile < ntiles) {
        for (int i = tid; i < 2048; i += THREADS) {
            int m = i & 31, kk = (i >> 5) & 7, pair = i >> 8;
            const float* xp = x + (size_t)(tile * TPT + pair * 2) * 1024 + kk * 32 + m;
            xs[i] = make_float2(xp[0], xp[1024]);
        }
    }
    __syncthreads();

    for (; tile < ntiles; tile += GRIDX) {
        // =================== stage 1 (k-chunked) ===================
        unsigned long long acc[4][2];
        #pragma unroll
        for (int qs = 0; qs < 4; qs++)
            #pragma unroll
            for (int pr = 0; pr < 2; pr++) acc[qs][pr] = 0ull;

        #pragma unroll
        for (int c = 0; c < NCHUNK; c++) {
            const int cur = c & 1;

            // -- prefetch next chunk (or next tile's chunk 0) into regs --
            float2 pf[4];
            bool doPf;
            int pfTokBase, pfKBase;
            if (c < NCHUNK - 1) {
                doPf = true; pfTokBase = tile * TPT; pfKBase = (c + 1) * KCH;
            } else {
                doPf = (tile + GRIDX) < ntiles;
                pfTokBase = (tile + GRIDX) * TPT; pfKBase = 0;
            }
            if (doPf) {
                #pragma unroll
                for (int i = 0; i < 4; i++) {
                    int lin = tid + i * THREADS;
                    int m = lin & 31, kk = (lin >> 5) & 7, pair = lin >> 8;
                    const float* xp = x + (size_t)(pfTokBase + pair * 2) * 1024
                                        + (pfKBase + kk) * 32 + m;
                    pf[i] = make_float2(xp[0], xp[1024]);
                }
            }

            // -- compute k = c*8 .. c*8+7 on xs[cur] --
            const float*  Lp = Ls + qq * 4096 + c * KCH * 32 + lane;  // + qs*1024 + kk*32
            const float2* vp = xs + cur * 2048 + pq * 512 + lane;     // + pr*256 + kk*32
            #pragma unroll
            for (int kk = 0; kk < KCH; kk++) {
                unsigned long long Lv[4];
                #pragma unroll
                for (int qs = 0; qs < 4; qs++)
                    Lv[qs] = pack2(Lp[qs * 1024 + kk * 32]);
                #pragma unroll
                for (int pr = 0; pr < 2; pr++) {
                    unsigned long long v =
                        *(const unsigned long long*)&vp[pr * 256 + kk * 32];
                    #pragma unroll
                    for (int qs = 0; qs < 4; qs++)
                        acc[qs][pr] = ffma2(Lv[qs], v, acc[qs][pr]);
                }
            }

            // -- commit prefetched chunk into the other buffer --
            if (doPf) {
                #pragma unroll
                for (int i = 0; i < 4; i++)
                    xs[(cur ^ 1) * 2048 + tid + i * THREADS] = pf[i];
            }
            __syncthreads();
        }

        // =================== h2 handoff (warp-private) ===================
        float2* hw = h2 + w * 256;     // [(qs*2+pr)*32 + m]
        #pragma unroll
        for (int qs = 0; qs < 4; qs++)
            #pragma unroll
            for (int pr = 0; pr < 2; pr++)
                *(unsigned long long*)&hw[(qs * 2 + pr) * 32 + lane] = acc[qs][pr];
        __syncwarp();

        // =================== stage 2 ===================
        {
            unsigned long long acc2[4][2];
            #pragma unroll
            for (int qs = 0; qs < 4; qs++)
                #pragma unroll
                for (int pr = 0; pr < 2; pr++) acc2[qs][pr] = 0ull;

            const float* Rp = Rs + qq * 4096 + lane;   // + qs*1024 + m*32
            #pragma unroll
            for (int m = 0; m < 32; m += 2) {
                #pragma unroll
                for (int qs = 0; qs < 4; qs++) {
                    unsigned long long R0 = pack2(Rp[qs * 1024 + m * 32]);
                    unsigned long long R1 = pack2(Rp[qs * 1024 + (m + 1) * 32]);
                    #pragma unroll
                    for (int pr = 0; pr < 2; pr++) {
                        // 16B broadcast: h[m], h[m+1] for this (qs,pr)
                        float4 hh = *(const float4*)&hw[(qs * 2 + pr) * 32 + m];
                        unsigned long long h0, h1;
                        asm("mov.b64 %0, {%1, %2};" : "=l"(h0) : "f"(hh.x), "f"(hh.y));
                        asm("mov.b64 %0, {%1, %2};" : "=l"(h1) : "f"(hh.z), "f"(hh.w));
                        acc2[qs][pr] = ffma2(R0, h0, acc2[qs][pr]);
                        acc2[qs][pr] = ffma2(R1, h1, acc2[qs][pr]);
                    }
                }
            }

            // stage2 result -> outs[t*528 + q*33 + p]   (lane = p)
            #pragma unroll
            for (int qs = 0; qs < 4; qs++)
                #pragma unroll
                for (int pr = 0; pr < 2; pr++) {
                    float f0, f1;
                    unpack2(acc2[qs][pr], f0, f1);
                    int t = pq * 4 + pr * 2;
                    int q = qq * 4 + qs;
                    outs[(t    ) * 528 + q * 33 + lane] = f0;
                    outs[(t + 1) * 528 + q * 33 + lane] = f1;
                }
        }
        __syncthreads();

        // =================== coalesced writeout ===================
        {
            const size_t gbase = (size_t)tile * TPT * 1024 + qb;
            #pragma unroll
            for (int i = 0; i < 16; i++) {
                int lin = tid + i * THREADS;          // < 8192
                int q = lin & 15;
                int p = (lin >> 4) & 31;
                int t = lin >> 9;
                out[gbase + (size_t)t * 1024 + p * 32 + q] =
                    outs[t * 528 + q * 33 + p];
            }
        }
        __syncthreads();   // outs + xs safe for next iteration
    }
}

extern "C" void kernel_launch(void* const* d_in, const int* in_sizes, int n_in,
                              void* d_out, int out_size)
{
    const float* x  = (const float*)d_in[0];
    const float* Lg = (const float*)d_in[1];
    const float* Rg = (const float*)d_in[2];
    float* out      = (float*)d_out;

    const int tokens = in_sizes[0] / 1024;   // 32768
    const int ntiles = tokens / TPT;         // 2048

    cudaFuncSetAttribute(monarch_kernel,
                         cudaFuncAttributeMaxDynamicSharedMemorySize, SMEM_BYTES);

    dim3 grid(GRIDX, 2);
    monarch_kernel<<<grid, THREADS, SMEM_BYTES>>>(x, Lg, Rg, out, ntiles);
}

// round 5
// speedup vs baseline: 1.0172x; 1.0001x over previous
#include <cuda_runtime.h>
#include <cstdint>

// MonarchOutProjection:
//   h2[t][m][q] = sum_k L[m][q][k] * x[t][32k+m]
//   out[t][32p+q] = sum_m R[q][p][m] * h2[t][m][q]
//
// R4 design:
//  - gridDim (74,2): q-half split (16 q per CTA), 148 CTAs = 1 wave, persistent.
//  - 512 threads (16 warps) -> occ 25% (was 12.5%).
//  - Tile = 16 tokens (8 f32x2 pairs). Warp w: qq = w&3 (4 q), pq = w>>2 (2 pairs).
//    q-reuse = 4, pair-reuse = 2  => ~2 B LDS per FMA (was ~2.5).
//  - x streamed in k-chunks of 8 via 2x8KB double buffer (LDG prefetch -> regs
//    -> STS commit), so full L+R halves + buffers fit 227KB smem.
//  - L stored [q][k][m], R stored [q][m][p]: lane-contiguous LDS, no padding.
//  - h2 staging is warp-private: stage1 warp (qq,pq) feeds stage2 warp (qq,pq),
//    only __syncwarp between stages. h-reads in stage2 are 16B broadcasts.

#define THREADS 512
#define GRIDX   74
#define TPT     16          // tokens per tile
#define KCH     8           // k-values per chunk
#define NCHUNK  4

// shared memory layout (float offsets)
#define OFF_LS   0          // Ls[q][k][m]           16*1024 = 16384
#define OFF_RS   16384      // Rs[q][m][p]           16*1024 = 16384
#define OFF_XS   32768      // xs: f2[2][8][8][32]   = 8192 floats
#define OFF_H2   40960      // h2: f2[16w][8][32]    = 8192 floats
#define OFF_OUT  49152      // outs[16t][16q*33+p]   = 8448 floats
#define SMEM_FLOATS 57600
#define SMEM_BYTES  (SMEM_FLOATS * 4)   // 230400 B

__device__ __forceinline__ unsigned long long pack2(float v) {
    unsigned long long r;
    asm("mov.b64 %0, {%1, %1};" : "=l"(r) : "f"(v));
    return r;
}
__device__ __forceinline__ unsigned long long ffma2(unsigned long long a,
                                                    unsigned long long b,
                                                    unsigned long long c) {
    unsigned long long d;
    asm("fma.rn.f32x2 %0, %1, %2, %3;" : "=l"(d) : "l"(a), "l"(b), "l"(c));
    return d;
}
__device__ __forceinline__ void unpack2(unsigned long long v, float& lo, float& hi) {
    asm("mov.b64 {%0, %1}, %2;" : "=f"(lo), "=f"(hi) : "l"(v));
}

__global__ __launch_bounds__(THREADS, 1)
void monarch_kernel(const float* __restrict__ x,
                    const float* __restrict__ Lg,
                    const float* __restrict__ Rg,
                    float* __restrict__ out,
                    int ntiles)
{
    extern __shared__ float sm[];
    float*  Ls   = sm + OFF_LS;
    float*  Rs   = sm + OFF_RS;
    float2* xs   = (float2*)(sm + OFF_XS);   // [buf*2048 + pair*256 + kk*32 + m]
    float2* h2   = (float2*)(sm + OFF_H2);   // [w*256 + (qs*2+pr)*32 + m]
    float*  outs = sm + OFF_OUT;             // [t*528 + q*33 + p]

    const int tid  = threadIdx.x;
    const int w    = tid >> 5;
    const int lane = tid & 31;
    const int qq   = w & 3;       // q quad: q_local = 4*qq + qs
    const int pq   = w >> 2;      // pair group: pairs {2pq, 2pq+1}
    const int qb   = blockIdx.y * 16;

    // ---- one-time L/R loads (global-coalesced reads, transposed STS) ----
    // Ls[q*1024 + k*32 + m] = Lg[m*1024 + (qb+q)*32 + k]
    for (int j = tid; j < 16384; j += THREADS) {
        int m = j >> 9;              // 0..31
        int r = j & 511;             // q*32 + k
        int q = r >> 5, k = r & 31;
        Ls[q * 1024 + k * 32 + m] = Lg[m * 1024 + qb * 32 + r];
    }
    // Rs[q*1024 + m*32 + p] = Rg[(qb+q)*1024 + p*32 + m]
    for (int j = tid; j < 16384; j += THREADS) {
        int q = j >> 10;
        int r = j & 1023;            // p*32 + m
        int p = r >> 5, m = r & 31;
        Rs[q * 1024 + m * 32 + p] = Rg[(qb + q) * 1024 + r];
    }

    int tile = blockIdx.x;

    // ---- preload chunk 0 of first tile into buf 0 ----
    if (tile < ntiles) {
        for (int i = tid; i < 2048; i += THREADS) {
            int m = i & 31, kk = (i >> 5) & 7, pair = i >> 8;
            const float* xp = x + (size_t)(tile * TPT + pair * 2) * 1024 + kk * 32 + m;
            xs[i] = make_float2(xp[0], xp[1024]);
        }
    }
    __syncthreads();

    for (; tile < ntiles; tile += GRIDX) {
        // =================== stage 1 (k-chunked) ===================
        unsigned long long acc[4][2];
        #pragma unroll
        for (int qs = 0; qs < 4; qs++)
            #pragma unroll
            for (int pr = 0; pr < 2; pr++) acc[qs][pr] = 0ull;

        #pragma unroll
        for (int c = 0; c < NCHUNK; c++) {
            const int cur = c & 1;

            // -- prefetch next chunk (or next tile's chunk 0) into regs --
            float2 pf[4];
            bool doPf;
            int pfTokBase, pfKBase;
            if (c < NCHUNK - 1) {
                doPf = true; pfTokBase = tile * TPT; pfKBase = (c + 1) * KCH;
            } else {
                doPf = (tile + GRIDX) < ntiles;
                pfTokBase = (tile + GRIDX) * TPT; pfKBase = 0;
            }
            if (doPf) {
                #pragma unroll
                for (int i = 0; i < 4; i++) {
                    int lin = tid + i * THREADS;
                    int m = lin & 31, kk = (lin >> 5) & 7, pair = lin >> 8;
                    const float* xp = x + (size_t)(pfTokBase + pair * 2) * 1024
                                        + (pfKBase + kk) * 32 + m;
                    pf[i] = make_float2(xp[0], xp[1024]);
                }
            }

            // -- compute k = c*8 .. c*8+7 on xs[cur] --
            const float*  Lp = Ls + qq * 4096 + c * KCH * 32 + lane;  // + qs*1024 + kk*32
            const float2* vp = xs + cur * 2048 + pq * 512 + lane;     // + pr*256 + kk*32
            #pragma unroll
            for (int kk = 0; kk < KCH; kk++) {
                unsigned long long Lv[4];
                #pragma unroll
                for (int qs = 0; qs < 4; qs++)
                    Lv[qs] = pack2(Lp[qs * 1024 + kk * 32]);
                #pragma unroll
                for (int pr = 0; pr < 2; pr++) {
                    unsigned long long v =
                        *(const unsigned long long*)&vp[pr * 256 + kk * 32];
                    #pragma unroll
                    for (int qs = 0; qs < 4; qs++)
                        acc[qs][pr] = ffma2(Lv[qs], v, acc[qs][pr]);
                }
            }

            // -- commit prefetched chunk into the other buffer --
            if (doPf) {
                #pragma unroll
                for (int i = 0; i < 4; i++)
                    xs[(cur ^ 1) * 2048 + tid + i * THREADS] = pf[i];
            }
            __syncthreads();
        }

        // =================== h2 handoff (warp-private) ===================
        float2* hw = h2 + w * 256;     // [(qs*2+pr)*32 + m]
        #pragma unroll
        for (int qs = 0; qs < 4; qs++)
            #pragma unroll
            for (int pr = 0; pr < 2; pr++)
                *(unsigned long long*)&hw[(qs * 2 + pr) * 32 + lane] = acc[qs][pr];
        __syncwarp();

        // =================== stage 2 ===================
        {
            unsigned long long acc2[4][2];
            #pragma unroll
            for (int qs = 0; qs < 4; qs++)
                #pragma unroll
                for (int pr = 0; pr < 2; pr++) acc2[qs][pr] = 0ull;

            const float* Rp = Rs + qq * 4096 + lane;   // + qs*1024 + m*32
            #pragma unroll
            for (int m = 0; m < 32; m += 2) {
                #pragma unroll
                for (int qs = 0; qs < 4; qs++) {
                    unsigned long long R0 = pack2(Rp[qs * 1024 + m * 32]);
                    unsigned long long R1 = pack2(Rp[qs * 1024 + (m + 1) * 32]);
                    #pragma unroll
                    for (int pr = 0; pr < 2; pr++) {
                        // 16B broadcast: h[m], h[m+1] for this (qs,pr)
                        float4 hh = *(const float4*)&hw[(qs * 2 + pr) * 32 + m];
                        unsigned long long h0, h1;
                        asm("mov.b64 %0, {%1, %2};" : "=l"(h0) : "f"(hh.x), "f"(hh.y));
                        asm("mov.b64 %0, {%1, %2};" : "=l"(h1) : "f"(hh.z), "f"(hh.w));
                        acc2[qs][pr] = ffma2(R0, h0, acc2[qs][pr]);
                        acc2[qs][pr] = ffma2(R1, h1, acc2[qs][pr]);
                    }
                }
            }

            // stage2 result -> outs[t*528 + q*33 + p]   (lane = p)
            #pragma unroll
            for (int qs = 0; qs < 4; qs++)
                #pragma unroll
                for (int pr = 0; pr < 2; pr++) {
                    float f0, f1;
                    unpack2(acc2[qs][pr], f0, f1);
                    int t = pq * 4 + pr * 2;
                    int q = qq * 4 + qs;
                    outs[(t    ) * 528 + q * 33 + lane] = f0;
                    outs[(t + 1) * 528 + q * 33 + lane] = f1;
                }
        }
        __syncthreads();

        // =================== coalesced writeout ===================
        {
            const size_t gbase = (size_t)tile * TPT * 1024 + qb;
            #pragma unroll
            for (int i = 0; i < 16; i++) {
                int lin = tid + i * THREADS;          // < 8192
                int q = lin & 15;
                int p = (lin >> 4) & 31;
                int t = lin >> 9;
                out[gbase + (size_t)t * 1024 + p * 32 + q] =
                    outs[t * 528 + q * 33 + p];
            }
        }
        __syncthreads();   // outs + xs safe for next iteration
    }
}

extern "C" void kernel_launch(void* const* d_in, const int* in_sizes, int n_in,
                              void* d_out, int out_size)
{
    const float* x  = (const float*)d_in[0];
    const float* Lg = (const float*)d_in[1];
    const float* Rg = (const float*)d_in[2];
    float* out      = (float*)d_out;

    const int tokens = in_sizes[0] / 1024;   // 32768
    const int ntiles = tokens / TPT;         // 2048

    cudaFuncSetAttribute(monarch_kernel,
                         cudaFuncAttributeMaxDynamicSharedMemorySize, SMEM_BYTES);

    dim3 grid(GRIDX, 2);
    monarch_kernel<<<grid, THREADS, SMEM_BYTES>>>(x, Lg, Rg, out, ntiles);
}

// round 6
// speedup vs baseline: 1.2517x; 1.2305x over previous
#include <cuda_runtime.h>
#include <cstdint>

// MonarchOutProjection:
//   h2[t][m][q]   = sum_k L[m][q][k] * x[t][32k+m]
//   out[t][32p+q] = sum_m R[q][p][m] * h2[t][m][q]
//
// R6 design (LSU-minimizing):
//  - grid (74,2): q-half split (16 q/CTA), 148 persistent CTAs = 1 wave.
//  - Tile = 32 tokens (16 f32x2 pairs). 512 threads / 16 warps.
//  - Stage1: lane=m. Warp (qg=w>>3, pg=w&7): q in [8qg,8qg+8), pairs {2pg,2pg+1}.
//    x loaded DIRECTLY from global into registers (double-buffered 4-k chunks);
//    no x smem at all. wf/ffma2 = 1/2 + 2/8 = 0.75.
//  - Stage2: warp w owns local q=w, lane=p. R[q][p][m] cached in 64 regs/tile
//    (32 LDS amortized over 512 ffma2); h2 read as float4 lane-broadcasts
//    (1 wf per 2 ffma2). Two half-passes (8 pairs each) so the outs staging
//    fits smem. wf/ffma2 ~ 0.56.
//  - smem: Ls 64KB [q][k][m] + Rs 64KB [q][m][p] + h2 64KB [q][pair][m]f32x2
//    + outs 34.8KB [16t][p*17+q]  = 231424 B.

#define THREADS 512
#define GRIDX   74
#define TPT     32

#define OFF_LS   0
#define OFF_RS   16384
#define OFF_H2   32768      // float2[16q][16pair][32m] = 16384 floats
#define OFF_OUT  49152      // outs[16t][544]           =  8704 floats
#define SMEM_FLOATS 57856
#define SMEM_BYTES  (SMEM_FLOATS * 4)   // 231424 B

typedef unsigned long long ull;

__device__ __forceinline__ ull pack2(float v) {
    ull r; asm("mov.b64 %0, {%1, %1};" : "=l"(r) : "f"(v)); return r;
}
__device__ __forceinline__ ull packpair(float a, float b) {
    ull r; asm("mov.b64 %0, {%1, %2};" : "=l"(r) : "f"(a), "f"(b)); return r;
}
__device__ __forceinline__ ull ffma2(ull a, ull b, ull c) {
    ull d; asm("fma.rn.f32x2 %0, %1, %2, %3;" : "=l"(d) : "l"(a), "l"(b), "l"(c));
    return d;
}
__device__ __forceinline__ void unpack2(ull v, float& lo, float& hi) {
    asm("mov.b64 {%0, %1}, %2;" : "=f"(lo), "=f"(hi) : "l"(v));
}

__global__ __launch_bounds__(THREADS, 1)
void monarch_kernel(const float* __restrict__ x,
                    const float* __restrict__ Lg,
                    const float* __restrict__ Rg,
                    float* __restrict__ out,
                    int ntiles)
{
    extern __shared__ float sm[];
    float*  Ls   = sm + OFF_LS;                 // [q*1024 + k*32 + m]
    float*  Rs   = sm + OFF_RS;                 // [q*1024 + m*32 + p]
    float2* h2   = (float2*)(sm + OFF_H2);      // [q*512 + pair*32 + m]
    float*  outs = sm + OFF_OUT;                // [t*544 + p*17 + q]

    const int tid  = threadIdx.x;
    const int w    = tid >> 5;
    const int lane = tid & 31;
    const int qg   = w >> 3;        // q in [8qg, 8qg+8)
    const int pg   = w & 7;         // pairs {2pg, 2pg+1} -> tokens [4pg, 4pg+4)
    const int qb   = blockIdx.y * 16;

    // ---- one-time weight staging (conflicts here are amortized away) ----
    for (int j = tid; j < 16384; j += THREADS) {
        int m = j >> 9, r = j & 511;            // r = q*32 + k
        Ls[(r >> 5) * 1024 + (r & 31) * 32 + m] = Lg[m * 1024 + qb * 32 + r];
    }
    for (int j = tid; j < 16384; j += THREADS) {
        int q = j >> 10, r = j & 1023;          // r = p*32 + m
        Rs[q * 1024 + (r & 31) * 32 + (r >> 5)] = Rg[(qb + q) * 1024 + r];
    }
    __syncthreads();

    int tile = blockIdx.x;

    // ---- register x double buffer: xr[buf][tok*4+kk] ----
    float xr[2][16];
    {
        int pt = (tile < ntiles) ? tile : 0;
        const float* pb = x + (size_t)(pt * TPT + 4 * pg) * 1024 + lane;
        #pragma unroll
        for (int t = 0; t < 4; t++)
            #pragma unroll
            for (int kk = 0; kk < 4; kk++)
                xr[0][t * 4 + kk] = pb[t * 1024 + kk * 32];
    }

    for (; tile < ntiles; tile += GRIDX) {
        // ===================== stage 1 =====================
        ull acc[8][2];
        #pragma unroll
        for (int qs = 0; qs < 8; qs++) { acc[qs][0] = 0ull; acc[qs][1] = 0ull; }

        const float* Lbase = Ls + qg * 8192 + lane;

        #pragma unroll 2
        for (int c = 0; c < 8; c++) {
            const int cb = c & 1;
            // prefetch next chunk (or next tile's chunk 0) — branchless clamp
            {
                int  ptile = (c < 7) ? tile : (tile + GRIDX);
                int  pk    = (c < 7) ? (c + 1) * 4 : 0;
                bool ok    = ptile < ntiles;
                int  st    = ok ? ptile : 0;
                const float* pb = x + (size_t)(st * TPT + 4 * pg) * 1024
                                    + pk * 32 + lane;
                #pragma unroll
                for (int t = 0; t < 4; t++)
                    #pragma unroll
                    for (int kk = 0; kk < 4; kk++)
                        xr[cb ^ 1][t * 4 + kk] = pb[t * 1024 + kk * 32];
            }
            // compute on chunk c
            #pragma unroll
            for (int kk = 0; kk < 4; kk++) {
                const int k = c * 4 + kk;
                ull v0 = packpair(xr[cb][0 * 4 + kk], xr[cb][1 * 4 + kk]);
                ull v1 = packpair(xr[cb][2 * 4 + kk], xr[cb][3 * 4 + kk]);
                const float* Lp = Lbase + k * 32;
                #pragma unroll
                for (int qs = 0; qs < 8; qs++) {
                    ull Lq = pack2(Lp[qs * 1024]);
                    acc[qs][0] = ffma2(Lq, v0, acc[qs][0]);
                    acc[qs][1] = ffma2(Lq, v1, acc[qs][1]);
                }
            }
        }

        // h2[q][pair][m] <- acc   (8B STS, conflict-free)
        #pragma unroll
        for (int qs = 0; qs < 8; qs++)
            #pragma unroll
            for (int pr = 0; pr < 2; pr++)
                *(ull*)&h2[((qg * 8 + qs) * 16 + 2 * pg + pr) * 32 + lane] =
                    acc[qs][pr];
        __syncthreads();                        // sync1: h2 complete

        // ===================== stage 2 =====================
        // R cache: 32 ull regs, reloaded per tile (cheap: 32 wf / 512 ffma2)
        ull rr[32];
        {
            const float* Rp = Rs + w * 1024 + lane;
            #pragma unroll
            for (int m = 0; m < 32; m++) rr[m] = pack2(Rp[m * 32]);
        }
        const float4* hq = (const float4*)(h2 + w * 512);  // [ (j*32+m)>>1 ]

        // ---- half A: pairs 0..7 (tokens 0..15) ----
        {
            ull a2[8];
            #pragma unroll
            for (int j = 0; j < 8; j++) a2[j] = 0ull;
            #pragma unroll
            for (int m = 0; m < 32; m += 2) {
                #pragma unroll
                for (int j = 0; j < 8; j++) {
                    float4 hh = hq[(j * 32 + m) >> 1];
                    ull h0 = packpair(hh.x, hh.y);
                    ull h1 = packpair(hh.z, hh.w);
                    a2[j] = ffma2(rr[m],     h0, a2[j]);
                    a2[j] = ffma2(rr[m + 1], h1, a2[j]);
                }
            }
            #pragma unroll
            for (int j = 0; j < 8; j++) {
                float f0, f1; unpack2(a2[j], f0, f1);
                outs[(2 * j)     * 544 + lane * 17 + w] = f0;
                outs[(2 * j + 1) * 544 + lane * 17 + w] = f1;
            }
        }
        __syncthreads();                        // sync2: outsA complete

        // writeout A: tokens tile*32 + [0,16)
        {
            const size_t gb = (size_t)tile * TPT * 1024 + qb;
            #pragma unroll
            for (int i = 0; i < 16; i++) {
                int lin = tid + i * THREADS;
                int q = lin & 15, p = (lin >> 4) & 31, t = lin >> 9;
                out[gb + (size_t)t * 1024 + p * 32 + q] =
                    outs[t * 544 + p * 17 + q];
            }
        }
        __syncthreads();                        // sync3: outs reusable

        // ---- half B: pairs 8..15 (tokens 16..31) ----
        {
            ull a2[8];
            #pragma unroll
            for (int j = 0; j < 8; j++) a2[j] = 0ull;
            #pragma unroll
            for (int m = 0; m < 32; m += 2) {
                #pragma unroll
                for (int j = 0; j < 8; j++) {
                    float4 hh = hq[((j + 8) * 32 + m) >> 1];
                    ull h0 = packpair(hh.x, hh.y);
                    ull h1 = packpair(hh.z, hh.w);
                    a2[j] = ffma2(rr[m],     h0, a2[j]);
                    a2[j] = ffma2(rr[m + 1], h1, a2[j]);
                }
            }
            #pragma unroll
            for (int j = 0; j < 8; j++) {
                float f0, f1; unpack2(a2[j], f0, f1);
                outs[(2 * j)     * 544 + lane * 17 + w] = f0;
                outs[(2 * j + 1) * 544 + lane * 17 + w] = f1;
            }
        }
        __syncthreads();                        // sync4: outsB complete

        // writeout B: tokens tile*32 + [16,32)  (overlaps next stage1)
        {
            const size_t gb = (size_t)(tile * TPT + 16) * 1024 + qb;
            #pragma unroll
            for (int i = 0; i < 16; i++) {
                int lin = tid + i * THREADS;
                int q = lin & 15, p = (lin >> 4) & 31, t = lin >> 9;
                out[gb + (size_t)t * 1024 + p * 32 + q] =
                    outs[t * 544 + p * 17 + q];
            }
        }
        // no trailing sync: next conflicting outs write is after next sync1/2.
    }
}

extern "C" void kernel_launch(void* const* d_in, const int* in_sizes, int n_in,
                              void* d_out, int out_size)
{
    const float* x  = (const float*)d_in[0];
    const float* Lg = (const float*)d_in[1];
    const float* Rg = (const float*)d_in[2];
    float* out      = (float*)d_out;

    const int tokens = in_sizes[0] / 1024;   // 32768
    const int ntiles = tokens / TPT;         // 1024

    cudaFuncSetAttribute(monarch_kernel,
                         cudaFuncAttributeMaxDynamicSharedMemorySize, SMEM_BYTES);

    dim3 grid(GRIDX, 2);
    monarch_kernel<<<grid, THREADS, SMEM_BYTES>>>(x, Lg, Rg, out, ntiles);
}